// round 2
// baseline (speedup 1.0000x reference)
#include <cuda_runtime.h>
#include <cuda_bf16.h>

// FrequencyAdaptiveNormSimple: out = sum_w softmax(alpha)[h,w] * (x - mu_w)/sd_w
// with sliding windows (5,10,20) over time, replicate-padded stats for t < w-1.
// B=32, T=2048, H=512, fp32. HBM-bound streaming kernel.

constexpr int Bc  = 32;
constexpr int Tc  = 2048;
constexpr int Hc  = 512;
constexpr int HCc = 128;          // h per block (= threads per block)
constexpr int TCc = 256;          // time chunk per block
constexpr int NCH = Tc / TCc;     // 8 time chunks
constexpr int NHB = Hc / HCc;     // 4 h chunks

static __device__ __forceinline__ float rsqrt_approx(float v) {
    float r;
    asm("rsqrt.approx.f32 %0, %1;" : "=f"(r) : "f"(v));
    return r;
}

template <int W>
static __device__ __forceinline__ float znorm(float xv, float s, float q) {
    const float invW   = 1.0f / (float)W;
    const float invWm1 = 1.0f / (float)(W - 1);
    float mu  = s * invW;
    float var = (q - (float)W * mu * mu) * invWm1;
    var = fmaxf(var, 0.0f);
    // sd = max(sqrt(var), 1e-4)  ->  invsd = (var > 1e-8) ? rsqrt(var) : 1e4
    float invsd = (var > 1e-8f) ? rsqrt_approx(var) : 1e4f;
    return (xv - mu) * invsd;
}

__global__ __launch_bounds__(HCc)
void fan_kernel(const float* __restrict__ x,
                const float* __restrict__ alpha,
                float* __restrict__ out)
{
    __shared__ float ring[20][HCc];  // last 20 x values, per-thread column
    __shared__ float ob[20][HCc];    // output accumulator for t<20 (chunk 0 only)

    const int tid   = threadIdx.x;
    int blk         = blockIdx.x;
    const int chunk = blk % NCH; blk /= NCH;
    const int hb    = blk % NHB; blk /= NHB;
    const int b     = blk;
    const int h     = hb * HCc + tid;

    const float* xp = x   + (size_t)b * Tc * Hc + h;
    float*       op = out + (size_t)b * Tc * Hc + h;

    // per-feature softmax over the 3 window weights
    float a0 = alpha[h * 3 + 0];
    float a1 = alpha[h * 3 + 1];
    float a2 = alpha[h * 3 + 2];
    float mx = fmaxf(a0, fmaxf(a1, a2));
    float e0 = __expf(a0 - mx), e1 = __expf(a1 - mx), e2 = __expf(a2 - mx);
    float ai = 1.0f / (e0 + e1 + e2);
    const float al5 = e0 * ai, al10 = e1 * ai, al20 = e2 * ai;

    float s5, q5, s10, q10, s20, q20;
    int tbeg;

    if (chunk == 0) {
        // ---- Phase A: t = 0..19 with replicate-padded stats ----
        #pragma unroll
        for (int t = 0; t < 20; t++) {
            ring[t][tid] = __ldg(&xp[t * Hc]);
            ob[t][tid]   = 0.0f;
        }
        // w = 5
        {
            float s = 0.f, q = 0.f;
            #pragma unroll
            for (int t = 0; t < 20; t++) {
                float v = ring[t][tid];
                s += v; q += v * v;
                if (t >= 5) { float l = ring[t - 5][tid]; s -= l; q -= l * l; }
                if (t == 4) {
                    #pragma unroll
                    for (int tp = 0; tp <= 4; tp++)
                        ob[tp][tid] += al5 * znorm<5>(ring[tp][tid], s, q);
                } else if (t > 4) {
                    ob[t][tid] += al5 * znorm<5>(v, s, q);
                }
            }
            s5 = s; q5 = q;
        }
        // w = 10
        {
            float s = 0.f, q = 0.f;
            #pragma unroll
            for (int t = 0; t < 20; t++) {
                float v = ring[t][tid];
                s += v; q += v * v;
                if (t >= 10) { float l = ring[t - 10][tid]; s -= l; q -= l * l; }
                if (t == 9) {
                    #pragma unroll
                    for (int tp = 0; tp <= 9; tp++)
                        ob[tp][tid] += al10 * znorm<10>(ring[tp][tid], s, q);
                } else if (t > 9) {
                    ob[t][tid] += al10 * znorm<10>(v, s, q);
                }
            }
            s10 = s; q10 = q;
        }
        // w = 20
        {
            float s = 0.f, q = 0.f;
            #pragma unroll
            for (int t = 0; t < 20; t++) {
                float v = ring[t][tid];
                s += v; q += v * v;
            }
            #pragma unroll
            for (int tp = 0; tp < 20; tp++)
                ob[tp][tid] += al20 * znorm<20>(ring[tp][tid], s, q);
            s20 = s; q20 = q;
        }
        #pragma unroll
        for (int t = 0; t < 20; t++)
            __stcs(&op[t * Hc], ob[t][tid]);
        tbeg = 20;
    } else {
        // ---- Halo warmup: sums over [t0-w, t0-1], ring holds x[t0-20..t0-1] ----
        const int t0 = chunk * TCc;
        s5 = q5 = s10 = q10 = s20 = q20 = 0.f;
        #pragma unroll
        for (int i = 0; i < 20; i++) {
            float v = __ldg(&xp[(t0 - 20 + i) * Hc]);
            ring[i][tid] = v;
            float v2 = v * v;
            s20 += v; q20 += v2;
            if (i >= 10) { s10 += v; q10 += v2; }
            if (i >= 15) { s5  += v; q5  += v2; }
        }
        tbeg = t0;
    }

    // ---- Steady state ----
    const int tend = chunk * TCc + TCc;
    int i20 = 0, i10 = 10, i5 = 15;   // ring slots of x[t-20], x[t-10], x[t-5]
    #pragma unroll 4
    for (int t = tbeg; t < tend; t++) {
        float xv  = __ldg(&xp[t * Hc]);
        float l20 = ring[i20][tid];
        float l10 = ring[i10][tid];
        float l5  = ring[i5][tid];
        float xv2 = xv * xv;
        s20 += xv - l20;  q20 += xv2 - l20 * l20;
        s10 += xv - l10;  q10 += xv2 - l10 * l10;
        s5  += xv - l5;   q5  += xv2 - l5 * l5;
        ring[i20][tid] = xv;
        i20 = (i20 == 19) ? 0 : i20 + 1;
        i10 = (i10 == 19) ? 0 : i10 + 1;
        i5  = (i5  == 19) ? 0 : i5  + 1;
        float o = al5  * znorm<5>(xv, s5, q5)
                + al10 * znorm<10>(xv, s10, q10)
                + al20 * znorm<20>(xv, s20, q20);
        __stcs(&op[t * Hc], o);
    }
}

extern "C" void kernel_launch(void* const* d_in, const int* in_sizes, int n_in,
                              void* d_out, int out_size) {
    const float* x     = (const float*)d_in[0];
    const float* alpha = (const float*)d_in[1];
    float*       out   = (float*)d_out;
    dim3 grid(Bc * NHB * NCH);   // 32 * 4 * 8 = 1024 blocks
    dim3 block(HCc);             // 128 threads
    fan_kernel<<<grid, block>>>(x, alpha, out);
}

// round 4
// speedup vs baseline: 1.6667x; 1.6667x over previous
#include <cuda_runtime.h>
#include <cuda_bf16.h>

// FrequencyAdaptiveNormSimple: out = sum_w softmax(alpha)[h,w] * (x - mu_w)/sd_w
// sliding windows (5,10,20), replicate-padded stats for t < w-1.
// B=32, T=2048, H=512 fp32. Register-ring version: time loop unrolled by 20,
// ring lives entirely in registers (no shared memory, no index ALU).

constexpr int Bc  = 32;
constexpr int Tc  = 2048;
constexpr int Hc  = 512;
constexpr int HCc = 128;          // h per block (= threads per block)
constexpr int TCc = 256;          // time chunk per block
constexpr int NCH = Tc / TCc;     // 8
constexpr int NHB = Hc / HCc;     // 4
static_assert(TCc % 20 == 16, "tail length assumed 16");

static __device__ __forceinline__ float rsq(float v) {
    float r;
    asm("rsqrt.approx.f32 %0, %1;" : "=f"(r) : "f"(v));
    return r;
}

// al * (xv - mu)/max(sd, 1e-4) with unbiased var, without any branch/select:
// invsd = rsqrt(max(var, 1e-8))  ==  1/max(sqrt(max(var,0)), 1e-4)
template <int W>
static __device__ __forceinline__ float zc(float xv, float s, float q, float al) {
    const float c1   = 1.0f / (float)(W - 1);
    const float c2   = 1.0f / ((float)W * (float)(W - 1));
    const float invW = 1.0f / (float)W;
    float var   = q * c1 - (s * c2) * s;
    float invsd = rsq(fmaxf(var, 1e-8f));
    return (xv - s * invW) * (al * invsd);
}

__global__ __launch_bounds__(HCc)
void fan_kernel(const float* __restrict__ x,
                const float* __restrict__ alpha,
                float* __restrict__ out)
{
    const int tid   = threadIdx.x;
    int blk         = blockIdx.x;
    const int chunk = blk % NCH; blk /= NCH;
    const int hb    = blk % NHB; blk /= NHB;
    const int b     = blk;
    const int h     = hb * HCc + tid;

    const float* xp = x   + (size_t)b * Tc * Hc + h;
    float*       op = out + (size_t)b * Tc * Hc + h;

    // per-feature softmax over 3 window weights
    float a0 = __ldg(&alpha[h * 3 + 0]);
    float a1 = __ldg(&alpha[h * 3 + 1]);
    float a2 = __ldg(&alpha[h * 3 + 2]);
    float mx = fmaxf(a0, fmaxf(a1, a2));
    float e0 = __expf(a0 - mx), e1 = __expf(a1 - mx), e2 = __expf(a2 - mx);
    float ai = 1.0f / (e0 + e1 + e2);
    const float al5 = e0 * ai, al10 = e1 * ai, al20 = e2 * ai;

    float r[20];                 // register ring: last 20 x values
    float s5, q5, s10, q10, s20, q20;
    int tbeg;

    if (chunk == 0) {
        // ---- t = 0..19 with replicate-padded leading stats ----
        float ob[20];
        #pragma unroll
        for (int t = 0; t < 20; t++) { r[t] = __ldg(&xp[t * Hc]); ob[t] = 0.0f; }

        // w = 5
        {
            float s = 0.f, q = 0.f;
            #pragma unroll
            for (int t = 0; t < 20; t++) {
                float v = r[t];
                s += v; q += v * v;
                if (t >= 5) { float l = r[t - 5]; s -= l; q -= l * l; }
                if (t == 4) {
                    #pragma unroll
                    for (int tp = 0; tp <= 4; tp++) ob[tp] += zc<5>(r[tp], s, q, al5);
                } else if (t > 4) {
                    ob[t] += zc<5>(v, s, q, al5);
                }
            }
            s5 = s; q5 = q;
        }
        // w = 10
        {
            float s = 0.f, q = 0.f;
            #pragma unroll
            for (int t = 0; t < 20; t++) {
                float v = r[t];
                s += v; q += v * v;
                if (t >= 10) { float l = r[t - 10]; s -= l; q -= l * l; }
                if (t == 9) {
                    #pragma unroll
                    for (int tp = 0; tp <= 9; tp++) ob[tp] += zc<10>(r[tp], s, q, al10);
                } else if (t > 9) {
                    ob[t] += zc<10>(v, s, q, al10);
                }
            }
            s10 = s; q10 = q;
        }
        // w = 20
        {
            float s = 0.f, q = 0.f;
            #pragma unroll
            for (int t = 0; t < 20; t++) { float v = r[t]; s += v; q += v * v; }
            #pragma unroll
            for (int tp = 0; tp < 20; tp++) ob[tp] += zc<20>(r[tp], s, q, al20);
            s20 = s; q20 = q;
        }
        #pragma unroll
        for (int t = 0; t < 20; t++) __stcs(&op[t * Hc], ob[t]);
        tbeg = 20;
        // ring invariant: r[(t - tbeg) % 20] == x[t-20]  (r[i] == x[i]) ✓
    } else {
        // ---- halo warmup: ring <- x[t0-20 .. t0-1], prefix sums ----
        const int t0 = chunk * TCc;
        const float* ph = xp + (size_t)(t0 - 20) * Hc;
        #pragma unroll
        for (int i = 0; i < 20; i++) r[i] = __ldg(&ph[i * Hc]);
        s5 = q5 = s10 = q10 = s20 = q20 = 0.f;
        #pragma unroll
        for (int i = 0; i < 20; i++) {
            float v = r[i], v2 = v * v;
            s20 += v; q20 += v2;
            if (i >= 10) { s10 += v; q10 += v2; }
            if (i >= 15) { s5  += v; q5  += v2; }
        }
        tbeg = t0;
    }

    const int tend = chunk * TCc + TCc;

    // ---- steady state: unroll-by-20, all ring indices compile-time ----
    int tb = tbeg;
    for (; tb + 20 <= tend; tb += 20) {
        const float* p = xp + (size_t)tb * Hc;
        float*       o = op + (size_t)tb * Hc;
        float xv[20];
        #pragma unroll
        for (int j = 0; j < 20; j++) xv[j] = __ldg(&p[j * Hc]);
        #pragma unroll
        for (int j = 0; j < 20; j++) {
            float v   = xv[j];
            float l20 = r[j];
            float l10 = r[(j + 10) % 20];
            float l5  = r[(j + 15) % 20];
            float v2  = v * v;
            s20 += v - l20;  q20 += v2 - l20 * l20;
            s10 += v - l10;  q10 += v2 - l10 * l10;
            s5  += v - l5;   q5  += v2 - l5 * l5;
            r[j] = v;
            float ov = zc<5>(v, s5, q5, al5)
                     + zc<10>(v, s10, q10, al10)
                     + zc<20>(v, s20, q20, al20);
            __stcs(&o[j * Hc], ov);
        }
    }

    // ---- fixed 16-step tail (ring base slot is 0 here) ----
    {
        const float* p = xp + (size_t)tb * Hc;
        float*       o = op + (size_t)tb * Hc;
        float xv[16];
        #pragma unroll
        for (int j = 0; j < 16; j++) xv[j] = __ldg(&p[j * Hc]);
        #pragma unroll
        for (int j = 0; j < 16; j++) {
            float v   = xv[j];
            float l20 = r[j];
            float l10 = r[(j + 10) % 20];
            float l5  = r[(j + 15) % 20];
            float v2  = v * v;
            s20 += v - l20;  q20 += v2 - l20 * l20;
            s10 += v - l10;  q10 += v2 - l10 * l10;
            s5  += v - l5;   q5  += v2 - l5 * l5;
            r[j] = v;
            float ov = zc<5>(v, s5, q5, al5)
                     + zc<10>(v, s10, q10, al10)
                     + zc<20>(v, s20, q20, al20);
            __stcs(&o[j * Hc], ov);
        }
    }
}

extern "C" void kernel_launch(void* const* d_in, const int* in_sizes, int n_in,
                              void* d_out, int out_size) {
    const float* x     = (const float*)d_in[0];
    const float* alpha = (const float*)d_in[1];
    float*       out   = (float*)d_out;
    dim3 grid(Bc * NHB * NCH);   // 1024 blocks
    dim3 block(HCc);             // 128 threads
    fan_kernel<<<grid, block>>>(x, alpha, out);
}